// round 2
// baseline (speedup 1.0000x reference)
#include <cuda_runtime.h>
#include <cuda_bf16.h>

// Row layout of z_1: [B, 16] fp32, row stride 64 bytes.
// Needed features: col0=line, col1=lx, col2=ly, col3=rx, col4=ry.
// cols 0-3 -> one float4 at row base (16B aligned, 64B row stride),
// col 4    -> scalar at byte offset 16; same 32B sector as the float4,
//             so each row costs exactly one DRAM sector for z_1.
// dir: [B, 8] fp32, one data-dependent float per row (one 32B sector).

__global__ __launch_bounds__(256) void slope_valuation_kernel(
    const float4* __restrict__ z4,   // z_1 viewed as float4 (4 per row)
    const float*  __restrict__ z,    // z_1 scalar view
    const float*  __restrict__ dir,  // [B, 8]
    float*        __restrict__ out,  // [B]
    int n)
{
    int i = blockIdx.x * blockDim.x + threadIdx.x;
    if (i >= n) return;

    // One 16B load covering cols 0..3
    float4 v = __ldg(&z4[(size_t)i * 4]);
    float line = v.x;
    float lx   = v.y;
    float ly   = v.z;
    float rx   = v.w;
    // col 4, same 32B sector as the float4 above
    float ry   = __ldg(&z[(size_t)i * 16 + 4]);

    float dx = rx - lx;
    float dy = -(ry - ly);

    // degrees(atan2) mapped to [0, 360)
    float phi = atan2f(dy, dx) * 57.29577951308232f;
    if (phi < 0.0f) phi += 360.0f;

    // clockwise shift; truncation == floor since phi >= 0
    int pcs = (90 + (int)phi) % 360;

    // area_angle = int(180/8) = 22, half = 11; exact in integer arithmetic
    int zone = ((pcs + 11) / 22) & 7;

    float picked = __ldg(&dir[(size_t)i * 8 + zone]);
    out[i] = (line != 0.0f) ? picked : 0.0f;
}

extern "C" void kernel_launch(void* const* d_in, const int* in_sizes, int n_in,
                              void* d_out, int out_size)
{
    const float* z_1 = (const float*)d_in[0];   // [B,16] fp32
    const float* dir = (const float*)d_in[1];   // [B,8]  fp32
    float* out = (float*)d_out;                 // [B]    fp32

    int n = in_sizes[0] / 16;                   // B rows

    int threads = 256;
    int blocks = (n + threads - 1) / threads;
    slope_valuation_kernel<<<blocks, threads>>>(
        (const float4*)z_1, z_1, dir, out, n);
}